// round 1
// baseline (speedup 1.0000x reference)
#include <cuda_runtime.h>
#include <cstdint>

#define Bb 64
#define Ss 512
#define Ff 512
#define Hh 1024
#define Oo 512

#define NBLK 96
#define TICKS 513           // t = 0..512 (tick t: layer0 step t, layer1 step t-1)
#define NBAR (TICKS * 2)

// ------------------------- persistent device state -------------------------
__device__ float    g_XP[(size_t)Bb * Ss * 2 * Hh];   // [b*S+t][2048] x-proj (f|c) + bias, 256 MB
__device__ float    g_Hcomb[Bb * 2 * Hh];             // [b][2048]  = [h0 | h1]
__device__ float    g_C[2 * Bb * Hh];                 // c0 then c1
__device__ float    g_P0[4 * Bb * 2 * Hh];            // layer0 partials [ksplit][b][2048]
__device__ float    g_P1[8 * Bb * 2 * Hh];            // layer1 partials [ksplit][b][2048]
__device__ unsigned g_bar[NBAR];

// ------------------------- helpers -------------------------
__device__ __forceinline__ float sigmoidf_(float v) {
    return 1.0f / (1.0f + expf(-v));
}

__device__ __forceinline__ void gridbar(int i) {
    __syncthreads();
    if (threadIdx.x == 0) {
        __threadfence();                       // release: partials/h visible in L2
        unsigned a = atomicAdd(&g_bar[i], 1u);
        if (a + 1u < (unsigned)NBLK) {
            volatile unsigned* p = &g_bar[i];
            while (*p < (unsigned)NBLK) { __nanosleep(64); }
        }
        __threadfence();                       // acquire-ish
    }
    __syncthreads();
}

// ------------------------- precompute: XP = x @ W[:F] + bias -------------------------
// C(32768 x 2048) = x(32768 x 512) @ [Wf0[:512] | Wc0[:512]](512 x 2048)
__global__ __launch_bounds__(256) void xproj_kernel(
    const float* __restrict__ x,
    const float* __restrict__ Wf0, const float* __restrict__ bf0,
    const float* __restrict__ Wc0, const float* __restrict__ bc0)
{
    __shared__ float As[128][17];
    __shared__ float Bs[16][128];

    int bx = blockIdx.x;                 // 0..15 : column tile (128 cols)
    int by = blockIdx.y;                 // 0..255: row tile (128 rows)
    int tid = threadIdx.x;
    int m0 = by * 128;
    int n0 = bx * 128;
    const float* Bsrc = (bx < 8) ? Wf0 : Wc0;
    const float* bias = (bx < 8) ? bf0 : bc0;
    int ncol = n0 & (Hh - 1);

    int r0 = (tid >> 4) * 8;             // 16 row groups
    int c0 = (tid & 15) * 8;             // 16 col groups

    float acc[8][8];
#pragma unroll
    for (int i = 0; i < 8; i++)
#pragma unroll
        for (int j = 0; j < 8; j++) acc[i][j] = 0.0f;

    for (int k0 = 0; k0 < Ff; k0 += 16) {
        // A tile: 128 x 16
#pragma unroll
        for (int q = 0; q < 2; q++) {
            int lin = q * 256 + tid;                 // float4 index 0..511
            int r = lin >> 2, kq = (lin & 3) * 4;
            float4 v = *reinterpret_cast<const float4*>(
                x + (size_t)(m0 + r) * Ff + k0 + kq);
            As[r][kq + 0] = v.x; As[r][kq + 1] = v.y;
            As[r][kq + 2] = v.z; As[r][kq + 3] = v.w;
        }
        // B tile: 16 x 128
#pragma unroll
        for (int q = 0; q < 2; q++) {
            int lin = q * 256 + tid;                 // float4 index 0..511
            int kk = lin >> 5, nq = (lin & 31) * 4;
            float4 v = *reinterpret_cast<const float4*>(
                Bsrc + (size_t)(k0 + kk) * Hh + ncol + nq);
            *reinterpret_cast<float4*>(&Bs[kk][nq]) = v;
        }
        __syncthreads();
#pragma unroll
        for (int kk = 0; kk < 16; kk++) {
            float a[8], b[8];
#pragma unroll
            for (int i = 0; i < 8; i++) a[i] = As[r0 + i][kk];
#pragma unroll
            for (int j = 0; j < 8; j++) b[j] = Bs[kk][c0 + j];
#pragma unroll
            for (int i = 0; i < 8; i++)
#pragma unroll
                for (int j = 0; j < 8; j++) acc[i][j] += a[i] * b[j];
        }
        __syncthreads();
    }
#pragma unroll
    for (int i = 0; i < 8; i++) {
#pragma unroll
        for (int j = 0; j < 8; j++) {
            g_XP[(size_t)(m0 + r0 + i) * (2 * Hh) + n0 + c0 + j] =
                acc[i][j] + bias[ncol + c0 + j];
        }
    }
}

// ------------------------- persistent recurrent kernel -------------------------
__global__ __launch_bounds__(256) void janet_recur(
    const float* __restrict__ Wf0, const float* __restrict__ Wc0,
    const float* __restrict__ Wf1, const float* __restrict__ bf1,
    const float* __restrict__ Wc1, const float* __restrict__ bc1)
{
    __shared__ float As[64][17];
    __shared__ float Bs[16][256];

    int bid = blockIdx.x, tid = threadIdx.x;

    // ---- block role: GEMM tile assignment ----
    int layer, nt, ks;
    const float* Bptr;
    float* Pout;
    if (bid < 32) {
        layer = 0; nt = bid & 7; ks = bid >> 3;                 // 8 ntiles x 4 ksplits
        Bptr = ((nt < 4) ? Wf0 : Wc0) + (size_t)Ff * Hh + (size_t)(nt & 3) * 256;
        Pout = g_P0 + (size_t)ks * (Bb * 2 * Hh);
    } else {
        int id = bid - 32;
        layer = 1; nt = id & 7; ks = id >> 3;                   // 8 ntiles x 8 ksplits
        Bptr = ((nt < 4) ? Wf1 : Wc1) + (size_t)(nt & 3) * 256;
        Pout = g_P1 + (size_t)ks * (Bb * 2 * Hh);
    }
    int kbase = ks * 256;
    int r0 = (tid >> 5) * 8;             // 8 row groups (warp-uniform -> broadcast LDS)
    int c0 = (tid & 31) * 8;             // 32 col groups -> 256 cols
    int ncolbase = nt * 256;
    int gtid = bid * 256 + tid;

    for (int t = 0; t < TICKS; t++) {
        // =============== phase G: GEMM partials ===============
        bool gActive = (layer == 0) ? (t < Ss) : (t >= 1);
        if (gActive) {
            float acc[8][8];
#pragma unroll
            for (int i = 0; i < 8; i++)
#pragma unroll
                for (int j = 0; j < 8; j++) acc[i][j] = 0.0f;

            for (int k0 = kbase; k0 < kbase + 256; k0 += 16) {
                // A tile: 64 x 16 from Hcomb (L1-bypass: written by other SMs)
                {
                    int r = tid >> 2, kq = (tid & 3) * 4;
                    float4 v = __ldcg(reinterpret_cast<const float4*>(
                        g_Hcomb + (size_t)r * (2 * Hh) + k0 + kq));
                    As[r][kq + 0] = v.x; As[r][kq + 1] = v.y;
                    As[r][kq + 2] = v.z; As[r][kq + 3] = v.w;
                }
                // B tile: 16 x 256 (read-only weights, L2-resident)
#pragma unroll
                for (int q = 0; q < 4; q++) {
                    int lin = q * 256 + tid;             // float4 index 0..1023
                    int kk = lin >> 6, nq = (lin & 63) * 4;
                    float4 v = *reinterpret_cast<const float4*>(
                        Bptr + (size_t)(k0 + kk) * Hh + nq);
                    *reinterpret_cast<float4*>(&Bs[kk][nq]) = v;
                }
                __syncthreads();
#pragma unroll
                for (int kk = 0; kk < 16; kk++) {
                    float a[8], b[8];
#pragma unroll
                    for (int i = 0; i < 8; i++) a[i] = As[r0 + i][kk];
#pragma unroll
                    for (int j = 0; j < 8; j++) b[j] = Bs[kk][c0 + j];
#pragma unroll
                    for (int i = 0; i < 8; i++)
#pragma unroll
                        for (int j = 0; j < 8; j++) acc[i][j] += a[i] * b[j];
                }
                __syncthreads();
            }
            // store partial tile
#pragma unroll
            for (int i = 0; i < 8; i++) {
#pragma unroll
                for (int j = 0; j < 8; j += 4) {
                    float4 v = make_float4(acc[i][j], acc[i][j + 1],
                                           acc[i][j + 2], acc[i][j + 3]);
                    *reinterpret_cast<float4*>(
                        Pout + (size_t)(r0 + i) * (2 * Hh) + ncolbase + c0 + j) = v;
                }
            }
        }
        gridbar(2 * t);

        // =============== phase R: reduce + activation + state update ===============
        for (int idx = gtid; idx < 2 * Bb * Hh; idx += NBLK * 256) {
            if (idx < Bb * Hh) {
                if (t < Ss) {                           // layer 0 step t
                    int b = idx >> 10, j = idx & (Hh - 1);
                    const float* xp = g_XP + ((size_t)(b * Ss + t)) * (2 * Hh);
                    float fpre = xp[j];
                    float cpre = xp[Hh + j];
#pragma unroll
                    for (int s = 0; s < 4; s++) {
                        const float* pp = g_P0 + (size_t)s * (Bb * 2 * Hh)
                                               + (size_t)b * (2 * Hh);
                        fpre += __ldcg(pp + j);
                        cpre += __ldcg(pp + Hh + j);
                    }
                    float f = sigmoidf_(fpre);
                    float ct = tanhf(cpre);
                    float cn = f * g_C[idx] + (1.0f - f) * ct;
                    g_C[idx] = cn;
                    g_Hcomb[(size_t)b * (2 * Hh) + j] = tanhf(cn);
                }
            } else {
                if (t >= 1) {                           // layer 1 step t-1
                    int idx2 = idx - Bb * Hh;
                    int b = idx2 >> 10, j = idx2 & (Hh - 1);
                    float fpre = bf1[j];
                    float cpre = bc1[j];
#pragma unroll
                    for (int s = 0; s < 8; s++) {
                        const float* pp = g_P1 + (size_t)s * (Bb * 2 * Hh)
                                               + (size_t)b * (2 * Hh);
                        fpre += __ldcg(pp + j);
                        cpre += __ldcg(pp + Hh + j);
                    }
                    float f = sigmoidf_(fpre);
                    float ct = tanhf(cpre);
                    float cn = f * g_C[Bb * Hh + idx2] + (1.0f - f) * ct;
                    g_C[Bb * Hh + idx2] = cn;
                    g_Hcomb[(size_t)b * (2 * Hh) + Hh + j] = tanhf(cn);
                }
            }
        }
        gridbar(2 * t + 1);
    }
}

// ------------------------- final projection: out = h1[last] @ Wfc + bfc -------------------------
__global__ __launch_bounds__(256) void proj_kernel(
    const float* __restrict__ Wfc, const float* __restrict__ bfc,
    float* __restrict__ out)
{
    int g = blockIdx.x * 256 + threadIdx.x;     // 0..32767
    int b = g >> 9, n = g & (Oo - 1);
    const float* h = g_Hcomb + (size_t)b * (2 * Hh) + Hh;
    float a0 = 0.f, a1 = 0.f, a2 = 0.f, a3 = 0.f;
    for (int k = 0; k < Hh; k += 4) {
        a0 += h[k + 0] * __ldg(Wfc + (size_t)(k + 0) * Oo + n);
        a1 += h[k + 1] * __ldg(Wfc + (size_t)(k + 1) * Oo + n);
        a2 += h[k + 2] * __ldg(Wfc + (size_t)(k + 2) * Oo + n);
        a3 += h[k + 3] * __ldg(Wfc + (size_t)(k + 3) * Oo + n);
    }
    out[g] = a0 + a1 + a2 + a3 + bfc[n];
}

// ------------------------- launch -------------------------
extern "C" void kernel_launch(void* const* d_in, const int* in_sizes, int n_in,
                              void* d_out, int out_size)
{
    (void)in_sizes; (void)n_in; (void)out_size;
    const float* x   = (const float*)d_in[0];
    const float* Wf0 = (const float*)d_in[1];
    const float* bf0 = (const float*)d_in[2];
    const float* Wc0 = (const float*)d_in[3];
    const float* bc0 = (const float*)d_in[4];
    const float* Wf1 = (const float*)d_in[5];
    const float* bf1 = (const float*)d_in[6];
    const float* Wc1 = (const float*)d_in[7];
    const float* bc1 = (const float*)d_in[8];
    const float* Wfc = (const float*)d_in[9];
    const float* bfc = (const float*)d_in[10];
    float* out = (float*)d_out;

    void *pH, *pC, *pBar;
    cudaGetSymbolAddress(&pH, g_Hcomb);
    cudaGetSymbolAddress(&pC, g_C);
    cudaGetSymbolAddress(&pBar, g_bar);
    cudaMemsetAsync(pH, 0, sizeof(float) * Bb * 2 * Hh);
    cudaMemsetAsync(pC, 0, sizeof(float) * 2 * Bb * Hh);
    cudaMemsetAsync(pBar, 0, sizeof(unsigned) * NBAR);

    dim3 gx(16, 256);
    xproj_kernel<<<gx, 256>>>(x, Wf0, bf0, Wc0, bc0);
    janet_recur<<<NBLK, 256>>>(Wf0, Wc0, Wf1, bf1, Wc1, bc1);
    proj_kernel<<<128, 256>>>(Wfc, bfc, out);
}

// round 3
// speedup vs baseline: 2.1786x; 2.1786x over previous
#include <cuda_runtime.h>
#include <cuda_bf16.h>
#include <cstdint>

#define Bb 64
#define Ss 512
#define Ff 512
#define Hh 1024
#define Oo 512

#define NBLK 96
#define TICKS 513           // tick t: layer0 step t, layer1 step t-1
#define NBAR (TICKS * 2)

// ------------------------- persistent device state -------------------------
__device__ float    g_XP[(size_t)Bb * Ss * 2 * Hh];   // x-proj (f|c) + bias
__device__ float    g_Hcomb[Bb * 2 * Hh];             // fp32 h (only h1 half maintained, for proj)
__device__ float    g_C[2 * Bb * Hh];                 // c0 then c1
__device__ float    g_P0[4 * Bb * 2 * Hh];            // layer0 partials [ksplit][b][2048]
__device__ float    g_P1[8 * Bb * 2 * Hh];            // layer1 partials [ksplit][b][2048]
__device__ unsigned g_bar[NBAR];

// A (h) in mma-fragment layout, split hi/lo bf16.
// A tile (16m x 16k): idx = (kt*4+mt)*256 + lane*8 + reg*2 + half
__device__ __nv_bfloat16 g_Ahi[64 * 2048];
__device__ __nv_bfloat16 g_Alo[64 * 2048];

// W in B-fragment layout, split hi/lo bf16. Tile (16k x 8n): 128 bf16, lane-major 4 bf16/lane.
// idx = (kt*256 + n8)*128 + lane*4 + reg*2 + half   (NT8 = 2048/8 = 256)
__device__ __nv_bfloat16 g_W0hi[1024 * 2048];
__device__ __nv_bfloat16 g_W0lo[1024 * 2048];
__device__ __nv_bfloat16 g_W1hi[2048 * 2048];
__device__ __nv_bfloat16 g_W1lo[2048 * 2048];

// ------------------------- helpers -------------------------
__device__ __forceinline__ float sigmoidf_(float v) {
    return 1.0f / (1.0f + expf(-v));
}

__device__ __forceinline__ void gridbar(int i) {
    __syncthreads();
    if (threadIdx.x == 0) {
        __threadfence();
        unsigned a = atomicAdd(&g_bar[i], 1u);
        if (a + 1u < (unsigned)NBLK) {
            volatile unsigned* p = &g_bar[i];
            while (*p < (unsigned)NBLK) { __nanosleep(64); }
        }
        __threadfence();
    }
    __syncthreads();
}

__device__ __forceinline__ void mma16816(float* c, const uint32_t* a, const uint32_t* b) {
    asm volatile(
        "mma.sync.aligned.m16n8k16.row.col.f32.bf16.bf16.f32 "
        "{%0,%1,%2,%3}, {%4,%5,%6,%7}, {%8,%9}, {%0,%1,%2,%3};"
        : "+f"(c[0]), "+f"(c[1]), "+f"(c[2]), "+f"(c[3])
        : "r"(a[0]), "r"(a[1]), "r"(a[2]), "r"(a[3]), "r"(b[0]), "r"(b[1]));
}

// ------------------------- weight prep: split + fragment-arrange -------------------------
__global__ __launch_bounds__(256) void prep_kernel(
    const float* __restrict__ Wf0, const float* __restrict__ Wc0,
    const float* __restrict__ Wf1, const float* __restrict__ Wc1)
{
    size_t i = (size_t)blockIdx.x * 256 + threadIdx.x;
    const size_t N0 = (size_t)1024 * 2048;
    float w;
    int k, n;
    __nv_bfloat16 *dhi, *dlo;
    if (i < N0) {
        k = (int)(i >> 11); n = (int)(i & 2047);
        w = (n < 1024) ? Wf0[(size_t)(512 + k) * 1024 + n]
                       : Wc0[(size_t)(512 + k) * 1024 + (n - 1024)];
        dhi = g_W0hi; dlo = g_W0lo;
    } else {
        size_t i2 = i - N0;
        k = (int)(i2 >> 11); n = (int)(i2 & 2047);
        w = (n < 1024) ? Wf1[(size_t)k * 1024 + n]
                       : Wc1[(size_t)k * 1024 + (n - 1024)];
        dhi = g_W1hi; dlo = g_W1lo;
    }
    __nv_bfloat16 hi = __float2bfloat16(w);
    __nv_bfloat16 lo = __float2bfloat16(w - __bfloat162float(hi));
    int kt = k >> 4, kk = k & 15;
    int lane = (n & 7) * 4 + ((kk & 7) >> 1);
    int reg = kk >> 3;
    size_t idx = ((size_t)(kt * 256 + (n >> 3))) * 128 + lane * 4 + reg * 2 + (kk & 1);
    dhi[idx] = hi;
    dlo[idx] = lo;
}

// ------------------------- precompute: XP = x @ W[:F] + bias -------------------------
__global__ __launch_bounds__(256) void xproj_kernel(
    const float* __restrict__ x,
    const float* __restrict__ Wf0, const float* __restrict__ bf0,
    const float* __restrict__ Wc0, const float* __restrict__ bc0)
{
    __shared__ float As[128][17];
    __shared__ float Bs[16][128];

    int bx = blockIdx.x;                 // 0..15 : column tile
    int by = blockIdx.y;                 // 0..255: row tile
    int tid = threadIdx.x;
    int m0 = by * 128;
    int n0 = bx * 128;
    const float* Bsrc = (bx < 8) ? Wf0 : Wc0;
    const float* bias = (bx < 8) ? bf0 : bc0;
    int ncol = n0 & (Hh - 1);

    int r0 = (tid >> 4) * 8;
    int c0 = (tid & 15) * 8;

    float acc[8][8];
#pragma unroll
    for (int i = 0; i < 8; i++)
#pragma unroll
        for (int j = 0; j < 8; j++) acc[i][j] = 0.0f;

    for (int k0 = 0; k0 < Ff; k0 += 16) {
#pragma unroll
        for (int q = 0; q < 2; q++) {
            int lin = q * 256 + tid;
            int r = lin >> 2, kq = (lin & 3) * 4;
            float4 v = *reinterpret_cast<const float4*>(
                x + (size_t)(m0 + r) * Ff + k0 + kq);
            As[r][kq + 0] = v.x; As[r][kq + 1] = v.y;
            As[r][kq + 2] = v.z; As[r][kq + 3] = v.w;
        }
#pragma unroll
        for (int q = 0; q < 2; q++) {
            int lin = q * 256 + tid;
            int kk = lin >> 5, nq = (lin & 31) * 4;
            float4 v = *reinterpret_cast<const float4*>(
                Bsrc + (size_t)(k0 + kk) * Hh + ncol + nq);
            *reinterpret_cast<float4*>(&Bs[kk][nq]) = v;
        }
        __syncthreads();
#pragma unroll
        for (int kk = 0; kk < 16; kk++) {
            float a[8], b[8];
#pragma unroll
            for (int i = 0; i < 8; i++) a[i] = As[r0 + i][kk];
#pragma unroll
            for (int j = 0; j < 8; j++) b[j] = Bs[kk][c0 + j];
#pragma unroll
            for (int i = 0; i < 8; i++)
#pragma unroll
                for (int j = 0; j < 8; j++) acc[i][j] += a[i] * b[j];
        }
        __syncthreads();
    }
#pragma unroll
    for (int i = 0; i < 8; i++) {
#pragma unroll
        for (int j = 0; j < 8; j++) {
            g_XP[(size_t)(m0 + r0 + i) * (2 * Hh) + n0 + c0 + j] =
                acc[i][j] + bias[ncol + c0 + j];
        }
    }
}

// ------------------------- persistent recurrent kernel (tensor-core) -------------------------
__global__ __launch_bounds__(256) void janet_recur(
    const float* __restrict__ bf1, const float* __restrict__ bc1)
{
    extern __shared__ __align__(16) char smem[];
    char* sAhi = smem;               // 32 KB: 16 ktiles x 4 mtiles x 512B
    char* sAlo = smem + 32768;       // 32 KB

    int bid = blockIdx.x, tid = threadIdx.x;
    int warp = tid >> 5, lane = tid & 31;

    // ---- block role ----
    int layer, nt, ks;
    const char *Whi, *Wlo;
    float* Pout;
    if (bid < 32) {
        layer = 0; nt = bid & 7; ks = bid >> 3;                 // 8 ntiles x 4 ksplits
        Whi = (const char*)g_W0hi; Wlo = (const char*)g_W0lo;
        Pout = g_P0 + (size_t)ks * (Bb * 2 * Hh);
    } else {
        int id = bid - 32;
        layer = 1; nt = id & 7; ks = id >> 3;                   // 8 ntiles x 8 ksplits
        Whi = (const char*)g_W1hi; Wlo = (const char*)g_W1lo;
        Pout = g_P1 + (size_t)ks * (Bb * 2 * Hh);
    }
    int ktb = ks * 16;                  // 16 ktiles (K=256) per block
    int ncolbase = nt * 256;
    int n8base = nt * 32 + warp * 4;    // warp covers 4 n-tiles of 8 (N=32)
    int gtid = bid * 256 + tid;
    int cg = lane >> 2, ct = lane & 3;  // C-fragment row/col decode

    for (int t = 0; t < TICKS; t++) {
        // =============== phase G: tensor-core GEMM partials ===============
        bool gActive = (layer == 0) ? (t < Ss) : (t >= 1);
        if (gActive) {
            // stage A slice (hi+lo) into smem, bypassing L1
            {
                const float4* srcH = (const float4*)((const char*)g_Ahi + (size_t)ktb * 2048);
                const float4* srcL = (const float4*)((const char*)g_Alo + (size_t)ktb * 2048);
                float4* dH = (float4*)sAhi;
                float4* dL = (float4*)sAlo;
#pragma unroll
                for (int q = 0; q < 8; q++) {
                    int p = q * 256 + tid;
                    dH[p] = __ldcg(srcH + p);
                    dL[p] = __ldcg(srcL + p);
                }
            }
            __syncthreads();

            float acc[4][4][4];
#pragma unroll
            for (int mt = 0; mt < 4; mt++)
#pragma unroll
                for (int n8 = 0; n8 < 4; n8++)
#pragma unroll
                    for (int q = 0; q < 4; q++) acc[mt][n8][q] = 0.0f;

            for (int ktl = 0; ktl < 16; ktl++) {
                int kt = ktb + ktl;
                uint32_t ah[4][4], al[4][4];
#pragma unroll
                for (int mt = 0; mt < 4; mt++) {
                    uint4 v = *(const uint4*)(sAhi + (ktl * 4 + mt) * 512 + lane * 16);
                    ah[mt][0] = v.x; ah[mt][1] = v.y; ah[mt][2] = v.z; ah[mt][3] = v.w;
                    uint4 w = *(const uint4*)(sAlo + (ktl * 4 + mt) * 512 + lane * 16);
                    al[mt][0] = w.x; al[mt][1] = w.y; al[mt][2] = w.z; al[mt][3] = w.w;
                }
                uint32_t bh[4][2], bl[4][2];
                size_t tbase = ((size_t)kt * 256 + n8base) * 256 + (size_t)lane * 8;
#pragma unroll
                for (int n8 = 0; n8 < 4; n8++) {
                    uint2 v = __ldg((const uint2*)(Whi + tbase + n8 * 256));
                    bh[n8][0] = v.x; bh[n8][1] = v.y;
                    uint2 w = __ldg((const uint2*)(Wlo + tbase + n8 * 256));
                    bl[n8][0] = w.x; bl[n8][1] = w.y;
                }
#pragma unroll
                for (int mt = 0; mt < 4; mt++) {
#pragma unroll
                    for (int n8 = 0; n8 < 4; n8++) {
                        mma16816(acc[mt][n8], ah[mt], bh[n8]);   // hi*hi
                        mma16816(acc[mt][n8], al[mt], bh[n8]);   // lo*hi
                        mma16816(acc[mt][n8], ah[mt], bl[n8]);   // hi*lo
                    }
                }
            }
            __syncthreads();

            // store partial tiles (fp32)
#pragma unroll
            for (int mt = 0; mt < 4; mt++) {
#pragma unroll
                for (int n8 = 0; n8 < 4; n8++) {
                    int mrow = mt * 16 + cg;
                    int col = ncolbase + warp * 32 + n8 * 8 + ct * 2;
                    float2 v0 = make_float2(acc[mt][n8][0], acc[mt][n8][1]);
                    float2 v1 = make_float2(acc[mt][n8][2], acc[mt][n8][3]);
                    *(float2*)(Pout + (size_t)mrow * (2 * Hh) + col) = v0;
                    *(float2*)(Pout + (size_t)(mrow + 8) * (2 * Hh) + col) = v1;
                }
            }
        }
        gridbar(2 * t);

        // =============== phase R: reduce + activation + state update ===============
        for (int idx = gtid; idx < 2 * Bb * Hh; idx += NBLK * 256) {
            if (idx < Bb * Hh) {
                if (t < Ss) {                           // layer 0 step t
                    int b = idx >> 10, j = idx & (Hh - 1);
                    const float* xp = g_XP + ((size_t)(b * Ss + t)) * (2 * Hh);
                    float fpre = xp[j];
                    float cpre = xp[Hh + j];
#pragma unroll
                    for (int s = 0; s < 4; s++) {
                        const float* pp = g_P0 + (size_t)s * (Bb * 2 * Hh)
                                               + (size_t)b * (2 * Hh);
                        fpre += __ldcg(pp + j);
                        cpre += __ldcg(pp + Hh + j);
                    }
                    float f = sigmoidf_(fpre);
                    float ctl = tanhf(cpre);
                    float cn = f * g_C[idx] + (1.0f - f) * ctl;
                    g_C[idx] = cn;
                    float h = tanhf(cn);
                    // write split h0 into A-fragment layout (A col k = j)
                    int k = j;
                    int kt = k >> 4, kk = k & 15, mt = b >> 4, r = b & 15;
                    int lane2 = (r & 7) * 4 + ((kk & 7) >> 1);
                    int reg = (r >> 3) + ((kk >> 3) << 1);
                    size_t aidx = (size_t)(kt * 4 + mt) * 256 + lane2 * 8 + reg * 2 + (kk & 1);
                    __nv_bfloat16 hh = __float2bfloat16(h);
                    g_Ahi[aidx] = hh;
                    g_Alo[aidx] = __float2bfloat16(h - __bfloat162float(hh));
                }
            } else {
                if (t >= 1) {                           // layer 1 step t-1
                    int idx2 = idx - Bb * Hh;
                    int b = idx2 >> 10, j = idx2 & (Hh - 1);
                    float fpre = bf1[j];
                    float cpre = bc1[j];
#pragma unroll
                    for (int s = 0; s < 8; s++) {
                        const float* pp = g_P1 + (size_t)s * (Bb * 2 * Hh)
                                               + (size_t)b * (2 * Hh);
                        fpre += __ldcg(pp + j);
                        cpre += __ldcg(pp + Hh + j);
                    }
                    float f = sigmoidf_(fpre);
                    float ctl = tanhf(cpre);
                    float cn = f * g_C[Bb * Hh + idx2] + (1.0f - f) * ctl;
                    g_C[Bb * Hh + idx2] = cn;
                    float h = tanhf(cn);
                    g_Hcomb[(size_t)b * (2 * Hh) + Hh + j] = h;   // fp32 for final proj
                    // write split h1 into A-fragment layout (A col k = 1024 + j)
                    int k = Hh + j;
                    int kt = k >> 4, kk = k & 15, mt = b >> 4, r = b & 15;
                    int lane2 = (r & 7) * 4 + ((kk & 7) >> 1);
                    int reg = (r >> 3) + ((kk >> 3) << 1);
                    size_t aidx = (size_t)(kt * 4 + mt) * 256 + lane2 * 8 + reg * 2 + (kk & 1);
                    __nv_bfloat16 hh = __float2bfloat16(h);
                    g_Ahi[aidx] = hh;
                    g_Alo[aidx] = __float2bfloat16(h - __bfloat162float(hh));
                }
            }
        }
        gridbar(2 * t + 1);
    }
}

// ------------------------- final projection: out = h1[last] @ Wfc + bfc -------------------------
__global__ __launch_bounds__(256) void proj_kernel(
    const float* __restrict__ Wfc, const float* __restrict__ bfc,
    float* __restrict__ out)
{
    int g = blockIdx.x * 256 + threadIdx.x;     // 0..32767
    int b = g >> 9, n = g & (Oo - 1);
    const float* h = g_Hcomb + (size_t)b * (2 * Hh) + Hh;
    float a0 = 0.f, a1 = 0.f, a2 = 0.f, a3 = 0.f;
    for (int k = 0; k < Hh; k += 4) {
        a0 += h[k + 0] * __ldg(Wfc + (size_t)(k + 0) * Oo + n);
        a1 += h[k + 1] * __ldg(Wfc + (size_t)(k + 1) * Oo + n);
        a2 += h[k + 2] * __ldg(Wfc + (size_t)(k + 2) * Oo + n);
        a3 += h[k + 3] * __ldg(Wfc + (size_t)(k + 3) * Oo + n);
    }
    out[g] = a0 + a1 + a2 + a3 + bfc[n];
}

// ------------------------- launch -------------------------
extern "C" void kernel_launch(void* const* d_in, const int* in_sizes, int n_in,
                              void* d_out, int out_size)
{
    (void)in_sizes; (void)n_in; (void)out_size;
    const float* x   = (const float*)d_in[0];
    const float* Wf0 = (const float*)d_in[1];
    const float* bf0 = (const float*)d_in[2];
    const float* Wc0 = (const float*)d_in[3];
    const float* bc0 = (const float*)d_in[4];
    const float* Wf1 = (const float*)d_in[5];
    const float* bf1 = (const float*)d_in[6];
    const float* Wc1 = (const float*)d_in[7];
    const float* bc1 = (const float*)d_in[8];
    const float* Wfc = (const float*)d_in[9];
    const float* bfc = (const float*)d_in[10];
    float* out = (float*)d_out;

    void *pH, *pC, *pBar, *pAhi, *pAlo;
    cudaGetSymbolAddress(&pH, g_Hcomb);
    cudaGetSymbolAddress(&pC, g_C);
    cudaGetSymbolAddress(&pBar, g_bar);
    cudaGetSymbolAddress(&pAhi, g_Ahi);
    cudaGetSymbolAddress(&pAlo, g_Alo);
    cudaMemsetAsync(pH, 0, sizeof(float) * Bb * 2 * Hh);
    cudaMemsetAsync(pC, 0, sizeof(float) * 2 * Bb * Hh);
    cudaMemsetAsync(pBar, 0, sizeof(unsigned) * NBAR);
    cudaMemsetAsync(pAhi, 0, sizeof(__nv_bfloat16) * 64 * 2048);
    cudaMemsetAsync(pAlo, 0, sizeof(__nv_bfloat16) * 64 * 2048);

    static int smem_set = 0;
    if (!smem_set) {
        cudaFuncSetAttribute(janet_recur,
                             cudaFuncAttributeMaxDynamicSharedMemorySize, 65536);
        smem_set = 1;
    }

    prep_kernel<<<24576, 256>>>(Wf0, Wc0, Wf1, Wc1);
    dim3 gx(16, 256);
    xproj_kernel<<<gx, 256>>>(x, Wf0, bf0, Wc0, bc0);
    janet_recur<<<NBLK, 256, 65536>>>(bf1, bc1);
    proj_kernel<<<128, 256>>>(Wfc, bfc, out);
}

// round 5
// speedup vs baseline: 2.7283x; 1.2523x over previous
#include <cuda_runtime.h>
#include <cuda_bf16.h>
#include <cstdint>

#define Bb 64
#define Ss 512
#define Ff 512
#define Hh 1024
#define Oo 512

#define NBLK 144
#define L0BLK 48
#define NS0 6
#define NS1 12
#define MAXKT 11
#define TICKS 513           // tick t: layer0 step t, layer1 step t-1
#define NBAR (TICKS * 2)

// ------------------------- persistent device state -------------------------
__device__ float    g_XP[(size_t)Bb * Ss * 2 * Hh];   // x-proj (f|c) + bias
__device__ float    g_Hcomb[Bb * 2 * Hh];             // fp32 h1 (for final proj)
__device__ float    g_C[2 * Bb * Hh];                 // c0 then c1
__device__ float    g_P0[NS0 * Bb * 2 * Hh];          // layer0 partials
__device__ float    g_P1[NS1 * Bb * 2 * Hh];          // layer1 partials
__device__ unsigned g_bar[NBAR];

// A (h) in mma-fragment layout, split hi/lo bf16 (mtile-minor):
// idx = (kt*4+mt)*256 + lane*8 + reg*2 + half
__device__ __nv_bfloat16 g_Ahi[64 * 2048];
__device__ __nv_bfloat16 g_Alo[64 * 2048];

// x in mma A-fragment layout (ktile-minor per mtile):
// idx = (mt*32 + kt)*256 + lane*8 + reg*2 + half
__device__ __nv_bfloat16 g_Xhi[(size_t)32768 * 512];
__device__ __nv_bfloat16 g_Xlo[(size_t)32768 * 512];

// W in B-fragment layout: idx = (kt*256 + n8)*128 + lane*4 + reg*2 + half
__device__ __nv_bfloat16 g_WXhi[512 * 2048];          // W0 rows 0..511 (x part)
__device__ __nv_bfloat16 g_WXlo[512 * 2048];
__device__ __nv_bfloat16 g_W0hi[1024 * 2048];         // W0 rows 512..1535 (h part)
__device__ __nv_bfloat16 g_W0lo[1024 * 2048];
__device__ __nv_bfloat16 g_W1hi[2048 * 2048];
__device__ __nv_bfloat16 g_W1lo[2048 * 2048];

// ------------------------- helpers -------------------------
__device__ __forceinline__ float sigmoidf_(float v) {
    return 1.0f / (1.0f + expf(-v));
}

__device__ __forceinline__ void gridbar(int i) {
    __syncthreads();
    if (threadIdx.x == 0) {
        __threadfence();
        unsigned a = atomicAdd(&g_bar[i], 1u);
        if (a + 1u < (unsigned)NBLK) {
            volatile unsigned* p = &g_bar[i];
            while (*p < (unsigned)NBLK) { __nanosleep(32); }
        }
        __threadfence();
    }
    __syncthreads();
}

__device__ __forceinline__ void mma16816(float* c, const uint32_t* a, const uint32_t* b) {
    asm volatile(
        "mma.sync.aligned.m16n8k16.row.col.f32.bf16.bf16.f32 "
        "{%0,%1,%2,%3}, {%4,%5,%6,%7}, {%8,%9}, {%0,%1,%2,%3};"
        : "+f"(c[0]), "+f"(c[1]), "+f"(c[2]), "+f"(c[3])
        : "r"(a[0]), "r"(a[1]), "r"(a[2]), "r"(a[3]), "r"(b[0]), "r"(b[1]));
}

// ------------------------- weight prep: split + B-fragment arrange -------------------------
__global__ __launch_bounds__(256) void prep_w(
    const float* __restrict__ Wf0, const float* __restrict__ Wc0,
    const float* __restrict__ Wf1, const float* __restrict__ Wc1)
{
    size_t i = (size_t)blockIdx.x * 256 + threadIdx.x;
    const size_t NX = (size_t)512 * 2048;
    const size_t N0 = (size_t)1024 * 2048;
    float w;
    int k, n;
    __nv_bfloat16 *dhi, *dlo;
    if (i < NX) {
        k = (int)(i >> 11); n = (int)(i & 2047);
        w = (n < 1024) ? Wf0[(size_t)k * 1024 + n]
                       : Wc0[(size_t)k * 1024 + (n - 1024)];
        dhi = g_WXhi; dlo = g_WXlo;
    } else if (i < NX + N0) {
        size_t i2 = i - NX;
        k = (int)(i2 >> 11); n = (int)(i2 & 2047);
        w = (n < 1024) ? Wf0[(size_t)(512 + k) * 1024 + n]
                       : Wc0[(size_t)(512 + k) * 1024 + (n - 1024)];
        dhi = g_W0hi; dlo = g_W0lo;
    } else {
        size_t i2 = i - NX - N0;
        k = (int)(i2 >> 11); n = (int)(i2 & 2047);
        w = (n < 1024) ? Wf1[(size_t)k * 1024 + n]
                       : Wc1[(size_t)k * 1024 + (n - 1024)];
        dhi = g_W1hi; dlo = g_W1lo;
    }
    __nv_bfloat16 hi = __float2bfloat16(w);
    __nv_bfloat16 lo = __float2bfloat16(w - __bfloat162float(hi));
    int kt = k >> 4, kk = k & 15;
    int lane = (n & 7) * 4 + ((kk & 7) >> 1);
    int reg = kk >> 3;
    size_t idx = ((size_t)(kt * 256 + (n >> 3))) * 128 + lane * 4 + reg * 2 + (kk & 1);
    dhi[idx] = hi;
    dlo[idx] = lo;
}

// ------------------------- x prep: split + A-fragment arrange (coalesced writes) -------------------------
__global__ __launch_bounds__(256) void prep_x(const float* __restrict__ x)
{
    size_t j = (size_t)blockIdx.x * 256 + threadIdx.x;   // handles bf16 pair (half 0,1)
    size_t lin = j * 2;
    int within = (int)(lin & 255);
    int lane = within >> 3;
    int reg = (within & 7) >> 1;
    size_t frag = lin >> 8;
    int kt = (int)(frag & 31);
    size_t mt = frag >> 5;
    int r  = (lane >> 2) + ((reg & 1) << 3);
    int kk = ((lane & 3) << 1) + ((reg >> 1) << 3);      // half=0; +1 for half=1
    size_t row = mt * 16 + r;
    int col = kt * 16 + kk;
    float v0 = x[row * Ff + col];
    float v1 = x[row * Ff + col + 1];
    __nv_bfloat16 h0 = __float2bfloat16(v0);
    __nv_bfloat16 h1 = __float2bfloat16(v1);
    __nv_bfloat16 l0 = __float2bfloat16(v0 - __bfloat162float(h0));
    __nv_bfloat16 l1 = __float2bfloat16(v1 - __bfloat162float(h1));
    __nv_bfloat162 ph; ph.x = h0; ph.y = h1;
    __nv_bfloat162 pl; pl.x = l0; pl.y = l1;
    reinterpret_cast<__nv_bfloat162*>(g_Xhi)[j] = ph;
    reinterpret_cast<__nv_bfloat162*>(g_Xlo)[j] = pl;
}

// ------------------------- tensor-core xproj: XP = x @ W0[:512] + bias -------------------------
__global__ __launch_bounds__(256) void xproj_tc(
    const float* __restrict__ bf0, const float* __restrict__ bc0)
{
    int nt = blockIdx.x;                 // 0..7 (N tile of 256)
    int by = blockIdx.y;                 // 0..511 (M tile of 64)
    int warp = threadIdx.x >> 5, lane = threadIdx.x & 31;
    int n8base = nt * 32 + warp * 4;
    int cg = lane >> 2, ct = lane & 3;
    const char* WXhi = (const char*)g_WXhi;
    const char* WXlo = (const char*)g_WXlo;

    float acc[4][4][4];
#pragma unroll
    for (int mt = 0; mt < 4; mt++)
#pragma unroll
        for (int n8 = 0; n8 < 4; n8++)
#pragma unroll
            for (int q = 0; q < 4; q++) acc[mt][n8][q] = 0.0f;

    for (int kt = 0; kt < 32; kt++) {
        uint32_t ah[4][4], al[4][4];
#pragma unroll
        for (int mt = 0; mt < 4; mt++) {
            size_t abase = ((size_t)(by * 4 + mt) * 32 + kt) * 256 + lane * 8;
            uint4 v = __ldg(reinterpret_cast<const uint4*>(g_Xhi + abase));
            ah[mt][0] = v.x; ah[mt][1] = v.y; ah[mt][2] = v.z; ah[mt][3] = v.w;
            uint4 w = __ldg(reinterpret_cast<const uint4*>(g_Xlo + abase));
            al[mt][0] = w.x; al[mt][1] = w.y; al[mt][2] = w.z; al[mt][3] = w.w;
        }
        uint32_t bh[4][2], bl[4][2];
        size_t tbase = ((size_t)kt * 256 + n8base) * 256 + (size_t)lane * 8;
#pragma unroll
        for (int n8 = 0; n8 < 4; n8++) {
            uint2 v = __ldg(reinterpret_cast<const uint2*>(WXhi + tbase + n8 * 256));
            bh[n8][0] = v.x; bh[n8][1] = v.y;
            uint2 w = __ldg(reinterpret_cast<const uint2*>(WXlo + tbase + n8 * 256));
            bl[n8][0] = w.x; bl[n8][1] = w.y;
        }
#pragma unroll
        for (int mt = 0; mt < 4; mt++)
#pragma unroll
            for (int n8 = 0; n8 < 4; n8++) {
                mma16816(acc[mt][n8], ah[mt], bh[n8]);
                mma16816(acc[mt][n8], al[mt], bh[n8]);
                mma16816(acc[mt][n8], ah[mt], bl[n8]);
            }
    }
#pragma unroll
    for (int mt = 0; mt < 4; mt++) {
#pragma unroll
        for (int n8 = 0; n8 < 4; n8++) {
            int gcol = nt * 256 + warp * 32 + n8 * 8 + ct * 2;
            size_t row = (size_t)by * 64 + mt * 16 + cg;
            float bb0 = (gcol < 1024) ? bf0[gcol] : bc0[gcol - 1024];
            float bb1 = (gcol + 1 < 1024) ? bf0[gcol + 1] : bc0[gcol + 1 - 1024];
            float2 v0 = make_float2(acc[mt][n8][0] + bb0, acc[mt][n8][1] + bb1);
            float2 v1 = make_float2(acc[mt][n8][2] + bb0, acc[mt][n8][3] + bb1);
            *reinterpret_cast<float2*>(g_XP + row * 2048 + gcol) = v0;
            *reinterpret_cast<float2*>(g_XP + (row + 8) * 2048 + gcol) = v1;
        }
    }
}

// ------------------------- persistent recurrent kernel (tensor-core) -------------------------
__global__ __launch_bounds__(256) void janet_recur(
    const float* __restrict__ bf1, const float* __restrict__ bc1)
{
    extern __shared__ __align__(16) char smem[];
    char* sAhi = smem;                       // MAXKT*4*512 = 22528 B
    char* sAlo = smem + MAXKT * 4 * 512;

    int bid = blockIdx.x, tid = threadIdx.x;
    int warp = tid >> 5, lane = tid & 31;

    // ---- block role ----
    int layer, nt, ks, ktb, cnt;
    const char *Whi, *Wlo;
    float* Pout;
    if (bid < L0BLK) {
        layer = 0; nt = bid & 7; ks = bid >> 3;                 // 8 nt x 6 ks over 64 ktiles
        ktb = 11 * ks - (ks > 4 ? (ks - 4) : 0);
        cnt = (ks < 4) ? 11 : 10;
        Whi = (const char*)g_W0hi; Wlo = (const char*)g_W0lo;
        Pout = g_P0 + (size_t)ks * (Bb * 2 * Hh);
    } else {
        int id = bid - L0BLK;
        layer = 1; nt = id & 7; ks = id >> 3;                   // 8 nt x 12 ks over 128 ktiles
        ktb = (ks < 8) ? 11 * ks : 88 + 10 * (ks - 8);
        cnt = (ks < 8) ? 11 : 10;
        Whi = (const char*)g_W1hi; Wlo = (const char*)g_W1lo;
        Pout = g_P1 + (size_t)ks * (Bb * 2 * Hh);
    }
    int ncolbase = nt * 256;
    int n8base = nt * 32 + warp * 4;
    int gtid = bid * 256 + tid;
    int cg = lane >> 2, ct = lane & 3;
    int nf4 = cnt * 128;                    // float4 per A buffer

    for (int t = 0; t < TICKS; t++) {
        // =============== phase G: tensor-core GEMM partials ===============
        bool gActive = (layer == 0) ? (t < Ss) : (t >= 1);
        if (gActive) {
            {
                const float4* srcH = (const float4*)((const char*)g_Ahi + (size_t)ktb * 2048);
                const float4* srcL = (const float4*)((const char*)g_Alo + (size_t)ktb * 2048);
                float4* dH = (float4*)sAhi;
                float4* dL = (float4*)sAlo;
                for (int p = tid; p < nf4; p += 256) {
                    dH[p] = __ldcg(srcH + p);
                    dL[p] = __ldcg(srcL + p);
                }
            }
            __syncthreads();

            float acc[4][4][4];
#pragma unroll
            for (int mt = 0; mt < 4; mt++)
#pragma unroll
                for (int n8 = 0; n8 < 4; n8++)
#pragma unroll
                    for (int q = 0; q < 4; q++) acc[mt][n8][q] = 0.0f;

            for (int ktl = 0; ktl < cnt; ktl++) {
                int kt = ktb + ktl;
                uint32_t ah[4][4], al[4][4];
#pragma unroll
                for (int mt = 0; mt < 4; mt++) {
                    uint4 v = *(const uint4*)(sAhi + (ktl * 4 + mt) * 512 + lane * 16);
                    ah[mt][0] = v.x; ah[mt][1] = v.y; ah[mt][2] = v.z; ah[mt][3] = v.w;
                    uint4 w = *(const uint4*)(sAlo + (ktl * 4 + mt) * 512 + lane * 16);
                    al[mt][0] = w.x; al[mt][1] = w.y; al[mt][2] = w.z; al[mt][3] = w.w;
                }
                uint32_t bh[4][2], bl[4][2];
                size_t tbase = ((size_t)kt * 256 + n8base) * 256 + (size_t)lane * 8;
#pragma unroll
                for (int n8 = 0; n8 < 4; n8++) {
                    uint2 v = __ldg((const uint2*)(Whi + tbase + n8 * 256));
                    bh[n8][0] = v.x; bh[n8][1] = v.y;
                    uint2 w = __ldg((const uint2*)(Wlo + tbase + n8 * 256));
                    bl[n8][0] = w.x; bl[n8][1] = w.y;
                }
#pragma unroll
                for (int mt = 0; mt < 4; mt++) {
#pragma unroll
                    for (int n8 = 0; n8 < 4; n8++) {
                        mma16816(acc[mt][n8], ah[mt], bh[n8]);   // hi*hi
                        mma16816(acc[mt][n8], al[mt], bh[n8]);   // lo*hi
                        mma16816(acc[mt][n8], ah[mt], bl[n8]);   // hi*lo
                    }
                }
            }
            __syncthreads();

#pragma unroll
            for (int mt = 0; mt < 4; mt++) {
#pragma unroll
                for (int n8 = 0; n8 < 4; n8++) {
                    int mrow = mt * 16 + cg;
                    int col = ncolbase + warp * 32 + n8 * 8 + ct * 2;
                    float2 v0 = make_float2(acc[mt][n8][0], acc[mt][n8][1]);
                    float2 v1 = make_float2(acc[mt][n8][2], acc[mt][n8][3]);
                    *(float2*)(Pout + (size_t)mrow * (2 * Hh) + col) = v0;
                    *(float2*)(Pout + (size_t)(mrow + 8) * (2 * Hh) + col) = v1;
                }
            }
        }
        gridbar(2 * t);

        // =============== phase R: reduce + activation + state update ===============
        for (int idx = gtid; idx < 2 * Bb * Hh; idx += NBLK * 256) {
            if (idx < Bb * Hh) {
                if (t < Ss) {                           // layer 0 step t
                    int b = idx >> 10, j = idx & (Hh - 1);
                    const float* xp = g_XP + ((size_t)(b * Ss + t)) * (2 * Hh);
                    float fpre = xp[j];
                    float cpre = xp[Hh + j];
#pragma unroll
                    for (int s = 0; s < NS0; s++) {
                        const float* pp = g_P0 + (size_t)s * (Bb * 2 * Hh)
                                               + (size_t)b * (2 * Hh);
                        fpre += __ldcg(pp + j);
                        cpre += __ldcg(pp + Hh + j);
                    }
                    float f = sigmoidf_(fpre);
                    float ctl = tanhf(cpre);
                    float cn = f * g_C[idx] + (1.0f - f) * ctl;
                    g_C[idx] = cn;
                    float h = tanhf(cn);
                    int k = j;
                    int kt = k >> 4, kk = k & 15, mt = b >> 4, r = b & 15;
                    int lane2 = (r & 7) * 4 + ((kk & 7) >> 1);
                    int reg = (r >> 3) + ((kk >> 3) << 1);
                    size_t aidx = (size_t)(kt * 4 + mt) * 256 + lane2 * 8 + reg * 2 + (kk & 1);
                    __nv_bfloat16 hh = __float2bfloat16(h);
                    g_Ahi[aidx] = hh;
                    g_Alo[aidx] = __float2bfloat16(h - __bfloat162float(hh));
                }
            } else {
                if (t >= 1) {                           // layer 1 step t-1
                    int idx2 = idx - Bb * Hh;
                    int b = idx2 >> 10, j = idx2 & (Hh - 1);
                    float fpre = bf1[j];
                    float cpre = bc1[j];
#pragma unroll
                    for (int s = 0; s < NS1; s++) {
                        const float* pp = g_P1 + (size_t)s * (Bb * 2 * Hh)
                                               + (size_t)b * (2 * Hh);
                        fpre += __ldcg(pp + j);
                        cpre += __ldcg(pp + Hh + j);
                    }
                    float f = sigmoidf_(fpre);
                    float ctl = tanhf(cpre);
                    float cn = f * g_C[Bb * Hh + idx2] + (1.0f - f) * ctl;
                    g_C[Bb * Hh + idx2] = cn;
                    float h = tanhf(cn);
                    g_Hcomb[(size_t)b * (2 * Hh) + Hh + j] = h;
                    int k = Hh + j;
                    int kt = k >> 4, kk = k & 15, mt = b >> 4, r = b & 15;
                    int lane2 = (r & 7) * 4 + ((kk & 7) >> 1);
                    int reg = (r >> 3) + ((kk >> 3) << 1);
                    size_t aidx = (size_t)(kt * 4 + mt) * 256 + lane2 * 8 + reg * 2 + (kk & 1);
                    __nv_bfloat16 hh = __float2bfloat16(h);
                    g_Ahi[aidx] = hh;
                    g_Alo[aidx] = __float2bfloat16(h - __bfloat162float(hh));
                }
            }
        }
        gridbar(2 * t + 1);
    }
}

// ------------------------- final projection: out = h1[last] @ Wfc + bfc -------------------------
__global__ __launch_bounds__(256) void proj_kernel(
    const float* __restrict__ Wfc, const float* __restrict__ bfc,
    float* __restrict__ out)
{
    int g = blockIdx.x * 256 + threadIdx.x;     // 0..32767
    int b = g >> 9, n = g & (Oo - 1);
    const float* h = g_Hcomb + (size_t)b * (2 * Hh) + Hh;
    float a0 = 0.f, a1 = 0.f, a2 = 0.f, a3 = 0.f;
    for (int k = 0; k < Hh; k += 4) {
        a0 += h[k + 0] * __ldg(Wfc + (size_t)(k + 0) * Oo + n);
        a1 += h[k + 1] * __ldg(Wfc + (size_t)(k + 1) * Oo + n);
        a2 += h[k + 2] * __ldg(Wfc + (size_t)(k + 2) * Oo + n);
        a3 += h[k + 3] * __ldg(Wfc + (size_t)(k + 3) * Oo + n);
    }
    out[g] = a0 + a1 + a2 + a3 + bfc[n];
}

// ------------------------- launch -------------------------
extern "C" void kernel_launch(void* const* d_in, const int* in_sizes, int n_in,
                              void* d_out, int out_size)
{
    (void)in_sizes; (void)n_in; (void)out_size;
    const float* x   = (const float*)d_in[0];
    const float* Wf0 = (const float*)d_in[1];
    const float* bf0 = (const float*)d_in[2];
    const float* Wc0 = (const float*)d_in[3];
    const float* bc0 = (const float*)d_in[4];
    const float* Wf1 = (const float*)d_in[5];
    const float* bf1 = (const float*)d_in[6];
    const float* Wc1 = (const float*)d_in[7];
    const float* bc1 = (const float*)d_in[8];
    const float* Wfc = (const float*)d_in[9];
    const float* bfc = (const float*)d_in[10];
    float* out = (float*)d_out;

    void *pH, *pC, *pBar, *pAhi, *pAlo;
    cudaGetSymbolAddress(&pH, g_Hcomb);
    cudaGetSymbolAddress(&pC, g_C);
    cudaGetSymbolAddress(&pBar, g_bar);
    cudaGetSymbolAddress(&pAhi, g_Ahi);
    cudaGetSymbolAddress(&pAlo, g_Alo);
    cudaMemsetAsync(pH, 0, sizeof(float) * Bb * 2 * Hh);
    cudaMemsetAsync(pC, 0, sizeof(float) * 2 * Bb * Hh);
    cudaMemsetAsync(pBar, 0, sizeof(unsigned) * NBAR);
    cudaMemsetAsync(pAhi, 0, sizeof(__nv_bfloat16) * 64 * 2048);
    cudaMemsetAsync(pAlo, 0, sizeof(__nv_bfloat16) * 64 * 2048);

    static int smem_set = 0;
    if (!smem_set) {
        cudaFuncSetAttribute(janet_recur,
                             cudaFuncAttributeMaxDynamicSharedMemorySize, 2 * MAXKT * 4 * 512);
        smem_set = 1;
    }

    prep_w<<<28672, 256>>>(Wf0, Wc0, Wf1, Wc1);
    prep_x<<<32768, 256>>>(x);
    dim3 gx(8, 512);
    xproj_tc<<<gx, 256>>>(bf0, bc0);
    janet_recur<<<NBLK, 256, 2 * MAXKT * 4 * 512>>>(bf1, bc1);
    proj_kernel<<<128, 256>>>(Wfc, bfc, out);
}

// round 6
// speedup vs baseline: 3.4755x; 1.2739x over previous
#include <cuda_runtime.h>
#include <cuda_bf16.h>
#include <cstdint>

#define Bb 64
#define Ss 512
#define Ff 512
#define Hh 1024
#define Oo 512

#define NBLK 144
#define L0BLK 48
#define NS0 6
#define NS1 12
#define MAXKT 11
#define TICKS 513           // tick t: layer0 step t, layer1 step t-1
#define NBAR (TICKS * 2)

// ------------------------- persistent device state -------------------------
__device__ float    g_XP[(size_t)Bb * Ss * 2 * Hh];   // x-proj (f|c) + bias
__device__ float    g_Hcomb[Bb * 2 * Hh];             // fp32 h1 (for final proj)
__device__ float    g_C[2 * Bb * Hh];                 // c0 then c1
__device__ float    g_P0[NS0 * Bb * 2 * Hh];          // layer0 partials
__device__ float    g_P1[NS1 * Bb * 2 * Hh];          // layer1 partials
__device__ unsigned g_bar[NBAR];

// A (h) in mma-fragment layout, split hi/lo bf16 (mtile-minor):
// idx = (kt*4+mt)*256 + lane*8 + reg*2 + half
__device__ __nv_bfloat16 g_Ahi[64 * 2048];
__device__ __nv_bfloat16 g_Alo[64 * 2048];

// x in mma A-fragment layout (ktile-minor per mtile)
__device__ __nv_bfloat16 g_Xhi[(size_t)32768 * 512];
__device__ __nv_bfloat16 g_Xlo[(size_t)32768 * 512];

// W in B-fragment layout: idx = (kt*256 + n8)*128 + lane*4 + reg*2 + half
__device__ __nv_bfloat16 g_WXhi[512 * 2048];          // W0 rows 0..511 (x part)
__device__ __nv_bfloat16 g_WXlo[512 * 2048];
__device__ __nv_bfloat16 g_W0hi[1024 * 2048];         // W0 rows 512..1535 (h part)
__device__ __nv_bfloat16 g_W0lo[1024 * 2048];
__device__ __nv_bfloat16 g_W1hi[2048 * 2048];
__device__ __nv_bfloat16 g_W1lo[2048 * 2048];

// ------------------------- helpers -------------------------
__device__ __forceinline__ float sigmoidf_(float v) {
    return 1.0f / (1.0f + expf(-v));
}

__device__ __forceinline__ void gridbar(int i) {
    __syncthreads();
    if (threadIdx.x == 0) {
        __threadfence();                               // release (covers CTA via prior syncthreads)
        atomicAdd(&g_bar[i], 1u);
        unsigned v;
        do {
            asm volatile("ld.acquire.gpu.global.u32 %0, [%1];"
                         : "=r"(v) : "l"(&g_bar[i]) : "memory");
        } while (v < (unsigned)NBLK);
    }
    __syncthreads();
}

__device__ __forceinline__ void mma16816(float* c, const uint32_t* a, const uint32_t* b) {
    asm volatile(
        "mma.sync.aligned.m16n8k16.row.col.f32.bf16.bf16.f32 "
        "{%0,%1,%2,%3}, {%4,%5,%6,%7}, {%8,%9}, {%0,%1,%2,%3};"
        : "+f"(c[0]), "+f"(c[1]), "+f"(c[2]), "+f"(c[3])
        : "r"(a[0]), "r"(a[1]), "r"(a[2]), "r"(a[3]), "r"(b[0]), "r"(b[1]));
}

__device__ __forceinline__ uint32_t packbf2(float a, float b) {
    __nv_bfloat162 p = __floats2bfloat162_rn(a, b);
    return *reinterpret_cast<uint32_t*>(&p);
}

// ------------------------- weight prep: split + B-fragment arrange -------------------------
__global__ __launch_bounds__(256) void prep_w(
    const float* __restrict__ Wf0, const float* __restrict__ Wc0,
    const float* __restrict__ Wf1, const float* __restrict__ Wc1)
{
    size_t i = (size_t)blockIdx.x * 256 + threadIdx.x;
    const size_t NX = (size_t)512 * 2048;
    const size_t N0 = (size_t)1024 * 2048;
    float w;
    int k, n;
    __nv_bfloat16 *dhi, *dlo;
    if (i < NX) {
        k = (int)(i >> 11); n = (int)(i & 2047);
        w = (n < 1024) ? Wf0[(size_t)k * 1024 + n]
                       : Wc0[(size_t)k * 1024 + (n - 1024)];
        dhi = g_WXhi; dlo = g_WXlo;
    } else if (i < NX + N0) {
        size_t i2 = i - NX;
        k = (int)(i2 >> 11); n = (int)(i2 & 2047);
        w = (n < 1024) ? Wf0[(size_t)(512 + k) * 1024 + n]
                       : Wc0[(size_t)(512 + k) * 1024 + (n - 1024)];
        dhi = g_W0hi; dlo = g_W0lo;
    } else {
        size_t i2 = i - NX - N0;
        k = (int)(i2 >> 11); n = (int)(i2 & 2047);
        w = (n < 1024) ? Wf1[(size_t)k * 1024 + n]
                       : Wc1[(size_t)k * 1024 + (n - 1024)];
        dhi = g_W1hi; dlo = g_W1lo;
    }
    __nv_bfloat16 hi = __float2bfloat16(w);
    __nv_bfloat16 lo = __float2bfloat16(w - __bfloat162float(hi));
    int kt = k >> 4, kk = k & 15;
    int lane = (n & 7) * 4 + ((kk & 7) >> 1);
    int reg = kk >> 3;
    size_t idx = ((size_t)(kt * 256 + (n >> 3))) * 128 + lane * 4 + reg * 2 + (kk & 1);
    dhi[idx] = hi;
    dlo[idx] = lo;
}

// ------------------------- x prep: split + A-fragment arrange -------------------------
__global__ __launch_bounds__(256) void prep_x(const float* __restrict__ x)
{
    size_t j = (size_t)blockIdx.x * 256 + threadIdx.x;   // handles bf16 pair (half 0,1)
    size_t lin = j * 2;
    int within = (int)(lin & 255);
    int lane = within >> 3;
    int reg = (within & 7) >> 1;
    size_t frag = lin >> 8;
    int kt = (int)(frag & 31);
    size_t mt = frag >> 5;
    int r  = (lane >> 2) + ((reg & 1) << 3);
    int kk = ((lane & 3) << 1) + ((reg >> 1) << 3);      // half=0; +1 for half=1
    size_t row = mt * 16 + r;
    int col = kt * 16 + kk;
    float v0 = x[row * Ff + col];
    float v1 = x[row * Ff + col + 1];
    __nv_bfloat16 h0 = __float2bfloat16(v0);
    __nv_bfloat16 h1 = __float2bfloat16(v1);
    __nv_bfloat16 l0 = __float2bfloat16(v0 - __bfloat162float(h0));
    __nv_bfloat16 l1 = __float2bfloat16(v1 - __bfloat162float(h1));
    __nv_bfloat162 ph; ph.x = h0; ph.y = h1;
    __nv_bfloat162 pl; pl.x = l0; pl.y = l1;
    reinterpret_cast<__nv_bfloat162*>(g_Xhi)[j] = ph;
    reinterpret_cast<__nv_bfloat162*>(g_Xlo)[j] = pl;
}

// ------------------------- tensor-core xproj: XP = x @ W0[:512] + bias -------------------------
__global__ __launch_bounds__(256) void xproj_tc(
    const float* __restrict__ bf0, const float* __restrict__ bc0)
{
    int nt = blockIdx.x;                 // 0..7 (N tile of 256)
    int by = blockIdx.y;                 // 0..511 (M tile of 64)
    int warp = threadIdx.x >> 5, lane = threadIdx.x & 31;
    int n8base = nt * 32 + warp * 4;
    int cg = lane >> 2, ct = lane & 3;
    const char* WXhi = (const char*)g_WXhi;
    const char* WXlo = (const char*)g_WXlo;

    float acc[4][4][4];
#pragma unroll
    for (int mt = 0; mt < 4; mt++)
#pragma unroll
        for (int n8 = 0; n8 < 4; n8++)
#pragma unroll
            for (int q = 0; q < 4; q++) acc[mt][n8][q] = 0.0f;

    for (int kt = 0; kt < 32; kt++) {
        uint32_t ah[4][4], al[4][4];
#pragma unroll
        for (int mt = 0; mt < 4; mt++) {
            size_t abase = ((size_t)(by * 4 + mt) * 32 + kt) * 256 + lane * 8;
            uint4 v = __ldg(reinterpret_cast<const uint4*>(g_Xhi + abase));
            ah[mt][0] = v.x; ah[mt][1] = v.y; ah[mt][2] = v.z; ah[mt][3] = v.w;
            uint4 w = __ldg(reinterpret_cast<const uint4*>(g_Xlo + abase));
            al[mt][0] = w.x; al[mt][1] = w.y; al[mt][2] = w.z; al[mt][3] = w.w;
        }
        uint32_t bh[4][2], bl[4][2];
        size_t tbase = ((size_t)kt * 256 + n8base) * 256 + (size_t)lane * 8;
#pragma unroll
        for (int n8 = 0; n8 < 4; n8++) {
            uint2 v = __ldg(reinterpret_cast<const uint2*>(WXhi + tbase + n8 * 256));
            bh[n8][0] = v.x; bh[n8][1] = v.y;
            uint2 w = __ldg(reinterpret_cast<const uint2*>(WXlo + tbase + n8 * 256));
            bl[n8][0] = w.x; bl[n8][1] = w.y;
        }
#pragma unroll
        for (int mt = 0; mt < 4; mt++)
#pragma unroll
            for (int n8 = 0; n8 < 4; n8++) {
                mma16816(acc[mt][n8], ah[mt], bh[n8]);
                mma16816(acc[mt][n8], al[mt], bh[n8]);
                mma16816(acc[mt][n8], ah[mt], bl[n8]);
            }
    }
#pragma unroll
    for (int mt = 0; mt < 4; mt++) {
#pragma unroll
        for (int n8 = 0; n8 < 4; n8++) {
            int gcol = nt * 256 + warp * 32 + n8 * 8 + ct * 2;
            size_t row = (size_t)by * 64 + mt * 16 + cg;
            float bb0 = (gcol < 1024) ? bf0[gcol] : bc0[gcol - 1024];
            float bb1 = (gcol + 1 < 1024) ? bf0[gcol + 1] : bc0[gcol + 1 - 1024];
            float2 v0 = make_float2(acc[mt][n8][0] + bb0, acc[mt][n8][1] + bb1);
            float2 v1 = make_float2(acc[mt][n8][2] + bb0, acc[mt][n8][3] + bb1);
            *reinterpret_cast<float2*>(g_XP + row * 2048 + gcol) = v0;
            *reinterpret_cast<float2*>(g_XP + (row + 8) * 2048 + gcol) = v1;
        }
    }
}

// ------------------------- persistent recurrent kernel (tensor-core) -------------------------
__global__ __launch_bounds__(256) void janet_recur(
    const float* __restrict__ bf1, const float* __restrict__ bc1)
{
    extern __shared__ __align__(16) char smem[];
    char* sAhi = smem;                       // MAXKT*4*512 = 22528 B
    char* sAlo = smem + MAXKT * 4 * 512;

    int bid = blockIdx.x, tid = threadIdx.x;
    int warp = tid >> 5, lane = tid & 31;

    // ---- block role: GEMM tile assignment ----
    int layer, nt, ks, ktb, cnt;
    const char *Whi, *Wlo;
    float* Pout;
    if (bid < L0BLK) {
        layer = 0; nt = bid & 7; ks = bid >> 3;                 // 8 nt x 6 ks over 64 ktiles
        ktb = 11 * ks - (ks > 4 ? (ks - 4) : 0);
        cnt = (ks < 4) ? 11 : 10;
        Whi = (const char*)g_W0hi; Wlo = (const char*)g_W0lo;
        Pout = g_P0 + (size_t)ks * (Bb * 2 * Hh);
    } else {
        int id = bid - L0BLK;
        layer = 1; nt = id & 7; ks = id >> 3;                   // 8 nt x 12 ks over 128 ktiles
        ktb = (ks < 8) ? 11 * ks : 88 + 10 * (ks - 8);
        cnt = (ks < 8) ? 11 : 10;
        Whi = (const char*)g_W1hi; Wlo = (const char*)g_W1lo;
        Pout = g_P1 + (size_t)ks * (Bb * 2 * Hh);
    }
    int ncolbase = nt * 256;
    int n8base = nt * 32 + warp * 4;
    int gtid = bid * 256 + tid;
    int cg = lane >> 2, ct = lane & 3;
    int nf4 = cnt * 128;                    // float4 per A buffer

    // ---- phase-R assignment: one half fragment line (4 bf16) per thread ----
    int r_hl = gtid & 1;
    int r_lane = (gtid >> 1) & 31;
    int r_mt = (gtid >> 6) & 3;
    int r_kt = gtid >> 8;                   // 0..127 for gtid < 32768
    bool r_valid = (gtid < 32768);
    bool r_isL0 = r_valid && (r_kt < 64);
    int r_b0 = r_mt * 16 + (r_lane >> 2);   // second row = r_b0 + 8
    int r_jj = (r_kt & 63) * 16 + ((r_lane & 3) << 1) + (r_hl << 3);  // pair (jj, jj+1)
    size_t r_uidx = (size_t)(r_kt * 4 + r_mt) * 64 + r_lane * 2 + r_hl;  // uint2 index

    for (int t = 0; t < TICKS; t++) {
        // =============== phase G: tensor-core GEMM partials ===============
        bool gActive = (layer == 0) ? (t < Ss) : (t >= 1);
        if (gActive) {
            {
                const float4* srcH = (const float4*)((const char*)g_Ahi + (size_t)ktb * 2048);
                const float4* srcL = (const float4*)((const char*)g_Alo + (size_t)ktb * 2048);
                float4* dH = (float4*)sAhi;
                float4* dL = (float4*)sAlo;
                for (int p = tid; p < nf4; p += 256) {
                    dH[p] = __ldcg(srcH + p);
                    dL[p] = __ldcg(srcL + p);
                }
            }
            __syncthreads();

            float acc[4][4][4];
#pragma unroll
            for (int mt = 0; mt < 4; mt++)
#pragma unroll
                for (int n8 = 0; n8 < 4; n8++)
#pragma unroll
                    for (int q = 0; q < 4; q++) acc[mt][n8][q] = 0.0f;

            for (int ktl = 0; ktl < cnt; ktl++) {
                int kt = ktb + ktl;
                uint32_t ah[4][4], al[4][4];
#pragma unroll
                for (int mt = 0; mt < 4; mt++) {
                    uint4 v = *(const uint4*)(sAhi + (ktl * 4 + mt) * 512 + lane * 16);
                    ah[mt][0] = v.x; ah[mt][1] = v.y; ah[mt][2] = v.z; ah[mt][3] = v.w;
                    uint4 w = *(const uint4*)(sAlo + (ktl * 4 + mt) * 512 + lane * 16);
                    al[mt][0] = w.x; al[mt][1] = w.y; al[mt][2] = w.z; al[mt][3] = w.w;
                }
                uint32_t bh[4][2], bl[4][2];
                size_t tbase = ((size_t)kt * 256 + n8base) * 256 + (size_t)lane * 8;
#pragma unroll
                for (int n8 = 0; n8 < 4; n8++) {
                    uint2 v = __ldg((const uint2*)(Whi + tbase + n8 * 256));
                    bh[n8][0] = v.x; bh[n8][1] = v.y;
                    uint2 w = __ldg((const uint2*)(Wlo + tbase + n8 * 256));
                    bl[n8][0] = w.x; bl[n8][1] = w.y;
                }
#pragma unroll
                for (int mt = 0; mt < 4; mt++) {
#pragma unroll
                    for (int n8 = 0; n8 < 4; n8++) {
                        mma16816(acc[mt][n8], ah[mt], bh[n8]);   // hi*hi
                        mma16816(acc[mt][n8], al[mt], bh[n8]);   // lo*hi
                        mma16816(acc[mt][n8], ah[mt], bl[n8]);   // hi*lo
                    }
                }
            }
            __syncthreads();

#pragma unroll
            for (int mt = 0; mt < 4; mt++) {
#pragma unroll
                for (int n8 = 0; n8 < 4; n8++) {
                    int mrow = mt * 16 + cg;
                    int col = ncolbase + warp * 32 + n8 * 8 + ct * 2;
                    float2 v0 = make_float2(acc[mt][n8][0], acc[mt][n8][1]);
                    float2 v1 = make_float2(acc[mt][n8][2], acc[mt][n8][3]);
                    *(float2*)(Pout + (size_t)mrow * (2 * Hh) + col) = v0;
                    *(float2*)(Pout + (size_t)(mrow + 8) * (2 * Hh) + col) = v1;
                }
            }
        }
        gridbar(2 * t);

        // =============== phase R: reduce + activation + state (coalesced fragment writes) ===============
        if (r_valid) {
            bool active = r_isL0 ? (t < Ss) : (t >= 1);
            if (active) {
                float fA0, fA1, cA0, cA1;   // (b0, jj), (b0, jj+1)
                float fB0, fB1, cB0, cB1;   // (b0+8, jj), (b0+8, jj+1)
                size_t cofs;
                if (r_isL0) {
                    const float* xpA = g_XP + ((size_t)r_b0 * Ss + t) * 2048 + r_jj;
                    const float* xpB = g_XP + ((size_t)(r_b0 + 8) * Ss + t) * 2048 + r_jj;
                    float2 a = *(const float2*)xpA;
                    float2 b = *(const float2*)(xpA + 1024);
                    float2 c = *(const float2*)xpB;
                    float2 d = *(const float2*)(xpB + 1024);
                    fA0 = a.x; fA1 = a.y; cA0 = b.x; cA1 = b.y;
                    fB0 = c.x; fB1 = c.y; cB0 = d.x; cB1 = d.y;
#pragma unroll
                    for (int s = 0; s < NS0; s++) {
                        const float* pA = g_P0 + (size_t)s * (Bb * 2 * Hh)
                                               + (size_t)r_b0 * 2048 + r_jj;
                        const float* pB = pA + (size_t)8 * 2048;
                        float2 u0 = __ldcg((const float2*)pA);
                        float2 u1 = __ldcg((const float2*)(pA + 1024));
                        float2 u2 = __ldcg((const float2*)pB);
                        float2 u3 = __ldcg((const float2*)(pB + 1024));
                        fA0 += u0.x; fA1 += u0.y; cA0 += u1.x; cA1 += u1.y;
                        fB0 += u2.x; fB1 += u2.y; cB0 += u3.x; cB1 += u3.y;
                    }
                    cofs = (size_t)r_b0 * 1024 + r_jj;
                    // prefetch next tick's XP rows into L2
                    if (t + 1 < Ss) {
                        asm volatile("prefetch.global.L2 [%0];" :: "l"(xpA + 2048));
                        asm volatile("prefetch.global.L2 [%0];" :: "l"(xpA + 2048 + 1024));
                        asm volatile("prefetch.global.L2 [%0];" :: "l"(xpB + 2048));
                        asm volatile("prefetch.global.L2 [%0];" :: "l"(xpB + 2048 + 1024));
                    }
                } else {
                    float2 bfv = *(const float2*)(bf1 + r_jj);
                    float2 bcv = *(const float2*)(bc1 + r_jj);
                    fA0 = bfv.x; fA1 = bfv.y; cA0 = bcv.x; cA1 = bcv.y;
                    fB0 = bfv.x; fB1 = bfv.y; cB0 = bcv.x; cB1 = bcv.y;
#pragma unroll
                    for (int s = 0; s < NS1; s++) {
                        const float* pA = g_P1 + (size_t)s * (Bb * 2 * Hh)
                                               + (size_t)r_b0 * 2048 + r_jj;
                        const float* pB = pA + (size_t)8 * 2048;
                        float2 u0 = __ldcg((const float2*)pA);
                        float2 u1 = __ldcg((const float2*)(pA + 1024));
                        float2 u2 = __ldcg((const float2*)pB);
                        float2 u3 = __ldcg((const float2*)(pB + 1024));
                        fA0 += u0.x; fA1 += u0.y; cA0 += u1.x; cA1 += u1.y;
                        fB0 += u2.x; fB1 += u2.y; cB0 += u3.x; cB1 += u3.y;
                    }
                    cofs = (size_t)(Bb * Hh) + (size_t)r_b0 * 1024 + r_jj;
                }
                float2 CA = *(float2*)(g_C + cofs);
                float2 CB = *(float2*)(g_C + cofs + 8 * 1024);
                float sA0 = sigmoidf_(fA0), sA1 = sigmoidf_(fA1);
                float sB0 = sigmoidf_(fB0), sB1 = sigmoidf_(fB1);
                float tA0 = tanhf(cA0), tA1 = tanhf(cA1);
                float tB0 = tanhf(cB0), tB1 = tanhf(cB1);
                float nA0 = sA0 * CA.x + (1.0f - sA0) * tA0;
                float nA1 = sA1 * CA.y + (1.0f - sA1) * tA1;
                float nB0 = sB0 * CB.x + (1.0f - sB0) * tB0;
                float nB1 = sB1 * CB.y + (1.0f - sB1) * tB1;
                *(float2*)(g_C + cofs) = make_float2(nA0, nA1);
                *(float2*)(g_C + cofs + 8 * 1024) = make_float2(nB0, nB1);
                float hA0 = tanhf(nA0), hA1 = tanhf(nA1);
                float hB0 = tanhf(nB0), hB1 = tanhf(nB1);
                if (!r_isL0) {      // keep fp32 h1 for the final projection
                    *(float2*)(g_Hcomb + (size_t)r_b0 * 2048 + 1024 + r_jj) =
                        make_float2(hA0, hA1);
                    *(float2*)(g_Hcomb + (size_t)(r_b0 + 8) * 2048 + 1024 + r_jj) =
                        make_float2(hB0, hB1);
                }
                // hi parts
                float hiA0 = __bfloat162float(__float2bfloat16(hA0));
                float hiA1 = __bfloat162float(__float2bfloat16(hA1));
                float hiB0 = __bfloat162float(__float2bfloat16(hB0));
                float hiB1 = __bfloat162float(__float2bfloat16(hB1));
                uint2 vh, vl;
                vh.x = packbf2(hA0, hA1);
                vh.y = packbf2(hB0, hB1);
                vl.x = packbf2(hA0 - hiA0, hA1 - hiA1);
                vl.y = packbf2(hB0 - hiB0, hB1 - hiB1);
                reinterpret_cast<uint2*>(g_Ahi)[r_uidx] = vh;
                reinterpret_cast<uint2*>(g_Alo)[r_uidx] = vl;
            }
        }
        gridbar(2 * t + 1);
    }
}

// ------------------------- final projection: out = h1[last] @ Wfc + bfc -------------------------
__global__ __launch_bounds__(256) void proj_kernel(
    const float* __restrict__ Wfc, const float* __restrict__ bfc,
    float* __restrict__ out)
{
    int g = blockIdx.x * 256 + threadIdx.x;     // 0..32767
    int b = g >> 9, n = g & (Oo - 1);
    const float* h = g_Hcomb + (size_t)b * (2 * Hh) + Hh;
    float a0 = 0.f, a1 = 0.f, a2 = 0.f, a3 = 0.f;
    for (int k = 0; k < Hh; k += 4) {
        a0 += h[k + 0] * __ldg(Wfc + (size_t)(k + 0) * Oo + n);
        a1 += h[k + 1] * __ldg(Wfc + (size_t)(k + 1) * Oo + n);
        a2 += h[k + 2] * __ldg(Wfc + (size_t)(k + 2) * Oo + n);
        a3 += h[k + 3] * __ldg(Wfc + (size_t)(k + 3) * Oo + n);
    }
    out[g] = a0 + a1 + a2 + a3 + bfc[n];
}

// ------------------------- launch -------------------------
extern "C" void kernel_launch(void* const* d_in, const int* in_sizes, int n_in,
                              void* d_out, int out_size)
{
    (void)in_sizes; (void)n_in; (void)out_size;
    const float* x   = (const float*)d_in[0];
    const float* Wf0 = (const float*)d_in[1];
    const float* bf0 = (const float*)d_in[2];
    const float* Wc0 = (const float*)d_in[3];
    const float* bc0 = (const float*)d_in[4];
    const float* Wf1 = (const float*)d_in[5];
    const float* bf1 = (const float*)d_in[6];
    const float* Wc1 = (const float*)d_in[7];
    const float* bc1 = (const float*)d_in[8];
    const float* Wfc = (const float*)d_in[9];
    const float* bfc = (const float*)d_in[10];
    float* out = (float*)d_out;

    void *pH, *pC, *pBar, *pAhi, *pAlo;
    cudaGetSymbolAddress(&pH, g_Hcomb);
    cudaGetSymbolAddress(&pC, g_C);
    cudaGetSymbolAddress(&pBar, g_bar);
    cudaGetSymbolAddress(&pAhi, g_Ahi);
    cudaGetSymbolAddress(&pAlo, g_Alo);
    cudaMemsetAsync(pH, 0, sizeof(float) * Bb * 2 * Hh);
    cudaMemsetAsync(pC, 0, sizeof(float) * 2 * Bb * Hh);
    cudaMemsetAsync(pBar, 0, sizeof(unsigned) * NBAR);
    cudaMemsetAsync(pAhi, 0, sizeof(__nv_bfloat16) * 64 * 2048);
    cudaMemsetAsync(pAlo, 0, sizeof(__nv_bfloat16) * 64 * 2048);

    static int smem_set = 0;
    if (!smem_set) {
        cudaFuncSetAttribute(janet_recur,
                             cudaFuncAttributeMaxDynamicSharedMemorySize, 2 * MAXKT * 4 * 512);
        smem_set = 1;
    }

    prep_w<<<28672, 256>>>(Wf0, Wc0, Wf1, Wc1);
    prep_x<<<32768, 256>>>(x);
    dim3 gx(8, 512);
    xproj_tc<<<gx, 256>>>(bf0, bc0);
    janet_recur<<<NBLK, 256, 2 * MAXKT * 4 * 512>>>(bf1, bc1);
    proj_kernel<<<128, 256>>>(Wfc, bfc, out);
}